// round 14
// baseline (speedup 1.0000x reference)
#include <cuda_runtime.h>

#define N_SAMPLES 32768
#define N_ITERS   16
#define KLEN      256
#define N_FRAMES  512
#define N_ATOMS   256
#define THREADS   1024
#define STEP      (N_SAMPLES / N_FRAMES)   // 64
#define N_VEC4    (N_SAMPLES / 4)          // 8192 float4s
#define W_VEC4    (KLEN / 4)               // 64 float4s per window
#define ZERO_BLOCKS 8
#define GRID      (1 + ZERO_BLOCKS)

// Monotone map: float bits -> u32 preserving < order (handles negatives).
__device__ __forceinline__ unsigned fkey(float v)
{
    unsigned u = __float_as_uint(v);
    return (u & 0x80000000u) ? ~u : (u | 0x80000000u);
}

// Vectorized warp argmax over NV float4s per lane (row length NV*128 floats).
// First-occurrence tie-break (jnp.argmax): within a lane by strict >, across
// lanes by redux-min over tied indices. Result broadcast to all lanes.
template <int NV>
__device__ __forceinline__ int warp_argmax_vec(const float4* __restrict__ row4, int lane)
{
    float bv = -3.402823466e38f;
    int   bi = 0x7fffffff;
    float4 rv[NV];
    #pragma unroll
    for (int c = 0; c < NV; c++) rv[c] = row4[lane + 32 * c];   // front-batched LDGs
    #pragma unroll
    for (int c = 0; c < NV; c++) {
        const int base = (lane + 32 * c) * 4;
        const float4 v = rv[c];
        if (v.x > bv) { bv = v.x; bi = base + 0; }
        if (v.y > bv) { bv = v.y; bi = base + 1; }
        if (v.z > bv) { bv = v.z; bi = base + 2; }
        if (v.w > bv) { bv = v.w; bi = base + 3; }
    }
    const unsigned key  = fkey(bv);
    const unsigned wmax = __reduce_max_sync(0xffffffffu, key);
    const unsigned cand = (key == wmax) ? (unsigned)bi : 0xffffffffu;
    return (int)__reduce_min_sync(0xffffffffu, cand);
}

__global__ __launch_bounds__(THREADS, 1)
void Model_67817533604348_kernel(const float* __restrict__ atom_sel,   // [16,256]
                                 const float* __restrict__ amps,       // [16,1]
                                 const float* __restrict__ sched,      // [16,512]
                                 const float* __restrict__ d,          // [256,256]
                                 float* __restrict__ out)              // [32768]
{
    __shared__ float s_atoms[N_ITERS][KLEN];           // 16 KB amp-scaled rows
    __shared__ __align__(16) int s_pos[N_ITERS];       // sample positions (mult 64)
    __shared__ float s_red[32];

    const int tid  = threadIdx.x;
    const int wid  = tid >> 5;
    const int lane = tid & 31;

    if (blockIdx.x != 0) {
        // ============ ZERO-WRITER BLOCKS (addresses disjoint from block 0) ======
        if (wid < N_ITERS) {
            int bi = warp_argmax_vec<4>((const float4*)(sched + wid * N_FRAMES), lane);
            if (lane == 0) s_pos[wid] = bi * STEP;     // sample position
        }
        __syncthreads();

        // one-time vector load of all 16 positions into registers
        int4 p4[4];
        #pragma unroll
        for (int q = 0; q < 4; q++)
            p4[q] = *reinterpret_cast<const int4*>(&s_pos[q * 4]);
        int p[N_ITERS];
        #pragma unroll
        for (int q = 0; q < 4; q++) {
            p[q*4+0] = p4[q].x; p[q*4+1] = p4[q].y;
            p[q*4+2] = p4[q].z; p[q*4+3] = p4[q].w;
        }

        const int v = (int)(blockIdx.x - 1) * THREADS + tid;   // float4 idx [0,8192)
        const int s = v << 2;                                  // sample idx
        bool covered = false;
        #pragma unroll
        for (int i = 0; i < N_ITERS; i++)
            covered |= ((unsigned)(s - p[i]) < (unsigned)KLEN);
        if (!covered)
            reinterpret_cast<float4*>(out)[v] = make_float4(0.f, 0.f, 0.f, 0.f);
        return;
    }

    // ================= COMPUTE BLOCK: windows only ============================
    // Warp w < 16: full pipeline for iter w — atom argmax -> fetch d row ->
    //              amp-scale -> stage to smem. (soft_dirac fwd = exact one-hot
    //              at argmax; softmax monotone -> raw-logit argmax suffices.)
    // Warp w >= 16: sched argmax for iter w-16 -> s_pos.
    if (wid < N_ITERS) {
        const int aidx = warp_argmax_vec<2>((const float4*)(atom_sel + wid * N_ATOMS),
                                            lane);
        const float amp = amps[wid];                       // broadcast LDG
        const float4* drow = (const float4*)(d + aidx * KLEN);
        const float4 d0 = drow[lane];                      // taps [4*lane, 4*lane+4)
        const float4 d1 = drow[lane + 32];                 // taps +128
        *reinterpret_cast<float4*>(&s_atoms[wid][lane * 4]) =
            make_float4(amp * d0.x, amp * d0.y, amp * d0.z, amp * d0.w);
        *reinterpret_cast<float4*>(&s_atoms[wid][lane * 4 + 128]) =
            make_float4(amp * d1.x, amp * d1.y, amp * d1.z, amp * d1.w);
    } else {
        const int i = wid - N_ITERS;
        int bi = warp_argmax_vec<4>((const float4*)(sched + i * N_FRAMES), lane);
        if (lane == 0) s_pos[i] = bi * STEP;   // sample position (multiple of 64)
    }
    __syncthreads();

    // one-time vector load of positions into registers (shortens dependent chain)
    int4 p4[4];
    #pragma unroll
    for (int q = 0; q < 4; q++)
        p4[q] = *reinterpret_cast<const int4*>(&s_pos[q * 4]);
    int p[N_ITERS];
    #pragma unroll
    for (int q = 0; q < 4; q++) {
        p[q*4+0] = p4[q].x; p[q*4+1] = p4[q].y;
        p[q*4+2] = p4[q].z; p[q*4+3] = p4[q].w;
    }

    // Gather: exactly one float4 of one window per thread. Own window always
    // covers (s0 - p[it] = k0 in [0,256)) -> unconditional; other 15 predicated.
    // s0 - p[j] is a multiple of 4 -> aligned LDS.128, conflict-free.
    // Overlapping windows give bitwise-identical duplicates — benign.
    const int it = tid >> 6;            // iter (64 threads per iter)
    const int k0 = (tid & 63) << 2;     // first tap, multiple of 4
    const int s0 = p[it] + k0;

    float4 acc = *reinterpret_cast<const float4*>(&s_atoms[it][k0]);
    #pragma unroll
    for (int j = 0; j < N_ITERS; j++) {
        if (j == it) continue;
        const int off = s0 - p[j];
        if ((unsigned)off < (unsigned)KLEN) {
            const float4 a = *reinterpret_cast<const float4*>(&s_atoms[j][off]);
            acc.x += a.x; acc.y += a.y; acc.z += a.z; acc.w += a.w;
        }
    }
    const bool ok = s0 < N_SAMPLES;   // truncated tail dropped (float4-aligned cut)

    // Block max-abs reduce. Values non-negative -> float bits compare as u32.
    // Stage 2 redundantly per warp (lane reads s_red[lane]) — only one BAR here.
    float mx = ok ? fmaxf(fmaxf(fabsf(acc.x), fabsf(acc.y)),
                          fmaxf(fabsf(acc.z), fabsf(acc.w))) : 0.0f;
    mx = __uint_as_float(__reduce_max_sync(0xffffffffu, __float_as_uint(mx)));
    if (lane == 0) s_red[wid] = mx;
    __syncthreads();
    const float m = __uint_as_float(
        __reduce_max_sync(0xffffffffu, __float_as_uint(s_red[lane])));
    const float scale = 1.0f / (m + 1e-8f);

    // Store ONLY window float4s (disjoint from zero-writers; duplicates on
    // overlapping windows carry identical bits — benign).
    if (ok) {
        acc.x *= scale; acc.y *= scale; acc.z *= scale; acc.w *= scale;
        *reinterpret_cast<float4*>(&out[s0]) = acc;
    }
}

extern "C" void kernel_launch(void* const* d_in, const int* in_sizes, int n_in,
                              void* d_out, int out_size) {
    // metadata order: x (unused), atom_selection, amps, sched_params, d
    const float* atom_sel = (const float*)d_in[1];
    const float* amps     = (const float*)d_in[2];
    const float* sched    = (const float*)d_in[3];
    const float* d        = (const float*)d_in[4];
    float* out            = (float*)d_out;

    Model_67817533604348_kernel<<<GRID, THREADS>>>(atom_sel, amps, sched, d, out);
}

// round 16
// speedup vs baseline: 1.2705x; 1.2705x over previous
#include <cuda_runtime.h>

#define N_SAMPLES 32768
#define N_ITERS   16
#define KLEN      256
#define N_FRAMES  512
#define N_ATOMS   256
#define THREADS   1024
#define STEP      (N_SAMPLES / N_FRAMES)   // 64
#define N_VEC4    (N_SAMPLES / 4)          // 8192 float4s
#define W_VEC4    (KLEN / 4)               // 64 float4s per window
#define ZERO_BLOCKS 8
#define GRID      (1 + ZERO_BLOCKS)

// Monotone map: float bits -> u32 preserving < order (handles negatives).
__device__ __forceinline__ unsigned fkey(float v)
{
    unsigned u = __float_as_uint(v);
    return (u & 0x80000000u) ? ~u : (u | 0x80000000u);
}

// Vectorized warp argmax over NV float4s per lane (row length NV*128 floats).
// First-occurrence tie-break (jnp.argmax): within a lane by strict >, across
// lanes by redux-min over tied indices. Result broadcast to all lanes.
// Uses redux.sync (1 instr) instead of 5-round shuffle trees.
template <int NV>
__device__ __forceinline__ int warp_argmax_vec(const float4* __restrict__ row4, int lane)
{
    float bv = -3.402823466e38f;
    int   bi = 0x7fffffff;
    float4 rv[NV];
    #pragma unroll
    for (int c = 0; c < NV; c++) rv[c] = row4[lane + 32 * c];   // front-batched LDGs
    #pragma unroll
    for (int c = 0; c < NV; c++) {
        const int base = (lane + 32 * c) * 4;
        const float4 v = rv[c];
        if (v.x > bv) { bv = v.x; bi = base + 0; }
        if (v.y > bv) { bv = v.y; bi = base + 1; }
        if (v.z > bv) { bv = v.z; bi = base + 2; }
        if (v.w > bv) { bv = v.w; bi = base + 3; }
    }
    const unsigned key  = fkey(bv);
    const unsigned wmax = __reduce_max_sync(0xffffffffu, key);
    const unsigned cand = (key == wmax) ? (unsigned)bi : 0xffffffffu;
    return (int)__reduce_min_sync(0xffffffffu, cand);
}

__global__ __launch_bounds__(THREADS, 1)
void Model_67817533604348_kernel(const float* __restrict__ atom_sel,   // [16,256]
                                 const float* __restrict__ amps,       // [16,1]
                                 const float* __restrict__ sched,      // [16,512]
                                 const float* __restrict__ d,          // [256,256]
                                 float* __restrict__ out)              // [32768]
{
    __shared__ float s_atoms[N_ITERS][KLEN];   // 16 KB: amp-scaled selected rows
    __shared__ int   s_pos[N_ITERS];           // block0: sample pos; zero: float4 pos
    __shared__ float s_red[32];

    const int tid  = threadIdx.x;
    const int wid  = tid >> 5;
    const int lane = tid & 31;

    if (blockIdx.x != 0) {
        // ================= ZERO-WRITER BLOCKS (addresses disjoint from block 0) ==
        if (wid < N_ITERS) {
            int bi = warp_argmax_vec<4>((const float4*)(sched + wid * N_FRAMES), lane);
            if (lane == 0) s_pos[wid] = (bi * STEP) >> 2;   // window start, float4s
        }
        __syncthreads();

        const int v = (int)(blockIdx.x - 1) * THREADS + tid;   // float4 idx [0,8192)
        bool covered = false;
        #pragma unroll
        for (int i = 0; i < N_ITERS; i++)
            covered |= ((unsigned)(v - s_pos[i]) < (unsigned)W_VEC4);
        if (!covered)
            reinterpret_cast<float4*>(out)[v] = make_float4(0.f, 0.f, 0.f, 0.f);
        return;
    }

    // ================= COMPUTE BLOCK: windows only ============================
    // Warp w < 16: full pipeline for iter w — atom argmax -> fetch d row ->
    //              amp-scale -> stage to smem. (soft_dirac fwd = exact one-hot
    //              at argmax; softmax monotone -> raw-logit argmax suffices.)
    // Warp w >= 16: sched argmax for iter w-16 -> s_pos.
    if (wid < N_ITERS) {
        const int aidx = warp_argmax_vec<2>((const float4*)(atom_sel + wid * N_ATOMS),
                                            lane);
        const float amp = amps[wid];                       // broadcast LDG
        const float4* drow = (const float4*)(d + aidx * KLEN);
        const float4 d0 = drow[lane];                      // taps [4*lane, 4*lane+4)
        const float4 d1 = drow[lane + 32];                 // taps +128
        *reinterpret_cast<float4*>(&s_atoms[wid][lane * 4]) =
            make_float4(amp * d0.x, amp * d0.y, amp * d0.z, amp * d0.w);
        *reinterpret_cast<float4*>(&s_atoms[wid][lane * 4 + 128]) =
            make_float4(amp * d1.x, amp * d1.y, amp * d1.z, amp * d1.w);
    } else {
        const int i = wid - N_ITERS;
        int bi = warp_argmax_vec<4>((const float4*)(sched + i * N_FRAMES), lane);
        if (lane == 0) s_pos[i] = bi * STEP;   // sample position (multiple of 64)
    }
    __syncthreads();

    // Gather: exactly one float4 of one window per thread. s0 - p_j is a
    // multiple of 4 (positions are multiples of 64) -> aligned LDS.128,
    // conflict-free. s_pos[j] reads use compile-time j (cheap broadcast LDS);
    // no dynamically-indexed register arrays (those demote to local memory).
    // Overlapping windows give bitwise-identical duplicates — benign.
    const int it = tid >> 6;            // iter (64 threads per iter)
    const int k0 = (tid & 63) << 2;     // first tap, multiple of 4
    const int s0 = s_pos[it] + k0;
    float4 acc = make_float4(0.f, 0.f, 0.f, 0.f);
    #pragma unroll
    for (int j = 0; j < N_ITERS; j++) {
        const int off = s0 - s_pos[j];
        if ((unsigned)off < (unsigned)KLEN) {
            const float4 a = *reinterpret_cast<const float4*>(&s_atoms[j][off]);
            acc.x += a.x; acc.y += a.y; acc.z += a.z; acc.w += a.w;
        }
    }
    const bool ok = s0 < N_SAMPLES;   // truncated tail dropped (float4-aligned cut)

    // Block max-abs reduce. Values are non-negative -> float bits compare as
    // u32, so redux.sync.max works directly. Stage 2 is done redundantly by
    // EVERY warp (each lane reads s_red[lane]) — no s_scale bounce, no 3rd BAR.
    float mx = ok ? fmaxf(fmaxf(fabsf(acc.x), fabsf(acc.y)),
                          fmaxf(fabsf(acc.z), fabsf(acc.w))) : 0.0f;
    mx = __uint_as_float(__reduce_max_sync(0xffffffffu, __float_as_uint(mx)));
    if (lane == 0) s_red[wid] = mx;
    __syncthreads();
    const float m = __uint_as_float(
        __reduce_max_sync(0xffffffffu, __float_as_uint(s_red[lane])));
    const float scale = 1.0f / (m + 1e-8f);

    // Store ONLY window float4s (disjoint from zero-writers; duplicates on
    // overlapping windows carry identical bits — benign).
    if (ok) {
        acc.x *= scale; acc.y *= scale; acc.z *= scale; acc.w *= scale;
        *reinterpret_cast<float4*>(&out[s0]) = acc;
    }
}

extern "C" void kernel_launch(void* const* d_in, const int* in_sizes, int n_in,
                              void* d_out, int out_size) {
    // metadata order: x (unused), atom_selection, amps, sched_params, d
    const float* atom_sel = (const float*)d_in[1];
    const float* amps     = (const float*)d_in[2];
    const float* sched    = (const float*)d_in[3];
    const float* d        = (const float*)d_in[4];
    float* out            = (float*)d_out;

    Model_67817533604348_kernel<<<GRID, THREADS>>>(atom_sel, amps, sched, d, out);
}